// round 8
// baseline (speedup 1.0000x reference)
#include <cuda_runtime.h>
#include <stdint.h>
#include <math.h>

#define BB 2
#define EE 1024
#define SS 2048
#define HH 16
#define DD 1024
#define DH 64
#define TQ 64
#define TK 32

// ---- scratch (static __device__ arrays; no allocations allowed) ----
__device__ float g_QP[(size_t)BB * DD * SS];
__device__ float g_KP[(size_t)BB * DD * SS];
__device__ float g_VP[(size_t)BB * DD * SS];
__device__ float g_AT[(size_t)BB * DD * SS];

__device__ __forceinline__ uint32_t f2tf(float x) {
    uint32_t u;
    asm("cvt.rna.tf32.f32 %0, %1;" : "=r"(u) : "f"(x));
    return u;
}

__device__ __forceinline__ void mma_tf32(float* c, const uint32_t* a, const uint32_t* b) {
    asm volatile(
        "mma.sync.aligned.m16n8k8.row.col.f32.tf32.tf32.f32 "
        "{%0,%1,%2,%3}, {%4,%5,%6,%7}, {%8,%9}, {%0,%1,%2,%3};"
        : "+f"(c[0]), "+f"(c[1]), "+f"(c[2]), "+f"(c[3])
        : "r"(a[0]), "r"(a[1]), "r"(a[2]), "r"(a[3]), "r"(b[0]), "r"(b[1]));
}

__device__ __forceinline__ void cp16(void* smem, const void* gmem) {
    uint32_t s = (uint32_t)__cvta_generic_to_shared(smem);
    asm volatile("cp.async.cg.shared.global [%0], [%1], 16;\n" :: "r"(s), "l"(gmem));
}
__device__ __forceinline__ void cp_commit() { asm volatile("cp.async.commit_group;\n"); }
template <int N>
__device__ __forceinline__ void cp_wait() { asm volatile("cp.async.wait_group %0;\n" :: "n"(N)); }

// ============================================================================
// Shared tf32 GEMM core: C[m,n] = sum_k A[m,k]*B[k,n] + bias[m].
// 128x128x16 tiles, 3-stage cp.async pipeline, 8 warps (2x4), 64x32 warp tile.
// ============================================================================
template <int BM, int BN>
__device__ __forceinline__ void gemm_core(
    const float* __restrict__ A, const float* __restrict__ Bmat,
    const float* __restrict__ bias, float* __restrict__ C,
    int K, int lda, int ldb, int ldc, int m0, int n0)
{
    constexpr int BK = 16;
    constexpr int THREADS = 256;
    constexpr int MT = 4, NT = 4;
    constexpr int AST = 20;
    constexpr int BST = BN + 8;
    constexpr int STG = 3;
    constexpr int AV = BM * BK / 4 / THREADS;
    constexpr int BV = BK * BN / 4 / THREADS;

    const int niter = K / BK;

    __shared__ __align__(16) float As[STG][BM * AST];
    __shared__ __align__(16) float Bs[STG][BK * BST];

    const int tid  = threadIdx.x;
    const int lane = tid & 31;
    const int wid  = tid >> 5;
    const int g    = lane >> 2;
    const int t    = lane & 3;
    const int wm   = (wid >> 2) * 64;
    const int wn   = (wid & 3) * 32;

    auto issue = [&](int it, int s) {
        const int k0 = it * BK;
        #pragma unroll
        for (int j = 0; j < AV; ++j) {
            int v = tid + j * THREADS;
            int mr = v / (BK / 4), c4 = (v % (BK / 4)) * 4;
            cp16(&As[s][mr * AST + c4], &A[(size_t)(m0 + mr) * lda + k0 + c4]);
        }
        #pragma unroll
        for (int j = 0; j < BV; ++j) {
            int v = tid + j * THREADS;
            int kr = v / (BN / 4), c4 = (v % (BN / 4)) * 4;
            cp16(&Bs[s][kr * BST + c4], &Bmat[(size_t)(k0 + kr) * ldb + n0 + c4]);
        }
        cp_commit();
    };

    float acc[MT][NT][4] = {};

    issue(0, 0);
    if (niter > 1) issue(1, 1);

    for (int i = 0; i < niter; ++i) {
        const int cur = i % STG;
        if (i + 1 < niter) cp_wait<1>(); else cp_wait<0>();
        __syncthreads();
        if (i + 2 < niter) issue(i + 2, (i + 2) % STG);

        #pragma unroll
        for (int ks = 0; ks < BK; ks += 8) {
            uint32_t af[MT][4], bf[NT][2];
            #pragma unroll
            for (int mt = 0; mt < MT; ++mt) {
                int row = wm + mt * 16 + g;
                af[mt][0] = f2tf(As[cur][row * AST + ks + t]);
                af[mt][1] = f2tf(As[cur][(row + 8) * AST + ks + t]);
                af[mt][2] = f2tf(As[cur][row * AST + ks + t + 4]);
                af[mt][3] = f2tf(As[cur][(row + 8) * AST + ks + t + 4]);
            }
            #pragma unroll
            for (int nt = 0; nt < NT; ++nt) {
                int col = wn + nt * 8 + g;
                bf[nt][0] = f2tf(Bs[cur][(ks + t) * BST + col]);
                bf[nt][1] = f2tf(Bs[cur][(ks + t + 4) * BST + col]);
            }
            #pragma unroll
            for (int mt = 0; mt < MT; ++mt)
                #pragma unroll
                for (int nt = 0; nt < NT; ++nt)
                    mma_tf32(acc[mt][nt], af[mt], bf[nt]);
        }
        __syncthreads();
    }

    #pragma unroll
    for (int mt = 0; mt < MT; ++mt) {
        int mg = m0 + wm + mt * 16 + g;
        float b0 = bias ? bias[mg] : 0.f;
        float b1 = bias ? bias[mg + 8] : 0.f;
        #pragma unroll
        for (int nt = 0; nt < NT; ++nt) {
            int n = n0 + wn + nt * 8 + 2 * t;
            float2 r0, r1;
            r0.x = acc[mt][nt][0] + b0;
            r0.y = acc[mt][nt][1] + b0;
            r1.x = acc[mt][nt][2] + b1;
            r1.y = acc[mt][nt][3] + b1;
            *reinterpret_cast<float2*>(&C[(size_t)mg * ldc + n]) = r0;
            *reinterpret_cast<float2*>(&C[(size_t)(mg + 8) * ldc + n]) = r1;
        }
    }
}

struct QKVParams {
    const float* W[3];
    const float* bias[3];
    const float* X[3];
    float* C[3];
};

// merged Q/K/V projections: z = mat*2 + batch
__global__ void __launch_bounds__(256, 2)
qkv_gemm(QKVParams p)
{
    const int mat = blockIdx.z >> 1;
    const int b   = blockIdx.z & 1;
    gemm_core<128, 128>(p.W[mat], p.X[mat] + (size_t)b * EE * SS, p.bias[mat],
                        p.C[mat] + (size_t)b * DD * SS,
                        EE, EE, SS, SS, blockIdx.y * 128, blockIdx.x * 128);
}

// output projection
__global__ void __launch_bounds__(256, 2)
out_gemm(const float* __restrict__ Wo, const float* __restrict__ AT,
         const float* __restrict__ bo, float* __restrict__ out)
{
    const int b = blockIdx.z;
    gemm_core<128, 128>(Wo, AT + (size_t)b * DD * SS, bo,
                        out + (size_t)b * DD * SS,
                        DD, DD, SS, SS, blockIdx.y * 128, blockIdx.x * 128);
}

// ============================================================================
// Fused flash attention. Block = (b*H+h, q-tile of 64). 256 threads, 8 warps.
// Double-buffered K/V (TK=32) via cp.async: tile kt+1 issued right after the
// top-of-iteration sync, overlapping all of compute(kt).
// qk_mask read only on diagonal tiles (k0+TK > q0); k_mask always added.
// Conflict-free smem strides: Qs/Ps 72, Ks 40, Vs 36.
// ============================================================================
__global__ void __launch_bounds__(256, 2)
flash_attn(const float* __restrict__ QP, const float* __restrict__ KP,
           const float* __restrict__ VP, const float* __restrict__ qk_mask,
           const float* __restrict__ k_mask, float* __restrict__ AT)
{
    extern __shared__ __align__(16) float smf[];
    float* Qs = smf;                       // [64 c][64 q] st 72
    float* Ks = Qs + 64 * 72;              // 2 x [64 c][32 k] st 40
    float* Vs = Ks + 2 * 64 * 40;          // 2 x [64 c][32 k] st 36
    float* Ps = Vs + 2 * 64 * 36;          // [32 k][64 q] st 72
    float* red = Ps + 32 * 72;             // [2][64]

    const int z   = blockIdx.y;
    const int b   = z / HH;
    const int q0  = blockIdx.x * TQ;
    const int tid  = threadIdx.x;
    const int lane = tid & 31;
    const int wid  = tid >> 5;
    const int g  = lane >> 2;
    const int t  = lane & 3;
    const int mh = wid >> 2;               // 0/1
    const int wq = (wid & 3) * 16;
    const int wk = mh * 16;                // MMA1 k-half
    const int wc = mh * 32;                // MMA2 c-half

    const float* Qg = QP + (size_t)z * DH * SS;
    const float* Kg = KP + (size_t)z * DH * SS;
    const float* Vg = VP + (size_t)z * DH * SS;
    const float* qm = qk_mask + (size_t)b * SS * SS;
    const float* km = k_mask + (size_t)b * SS;

    // Q tile: 64 rows x 64 cols
    #pragma unroll
    for (int j = 0; j < 4; ++j) {
        int v = tid + j * 256;
        int r = v >> 4, c4 = (v & 15) << 2;
        cp16(&Qs[r * 72 + c4], &Qg[(size_t)r * SS + q0 + c4]);
    }
    cp_commit();

    auto issue = [&](int kt, int s) {
        const int k0 = kt * TK;
        #pragma unroll
        for (int j = 0; j < 2; ++j) {
            int v = tid + j * 256;
            int r = v >> 3, c4 = (v & 7) << 2;
            cp16(&Ks[s * 64 * 40 + r * 40 + c4], &Kg[(size_t)r * SS + k0 + c4]);
            cp16(&Vs[s * 64 * 36 + r * 36 + c4], &Vg[(size_t)r * SS + k0 + c4]);
        }
        cp_commit();
    };

    float accO[2][2][4] = {};
    float mC[4], lC[4];
    #pragma unroll
    for (int i = 0; i < 4; ++i) { mC[i] = -1e30f; lC[i] = 0.f; }

    const int nkt = q0 / TK + 2;
    issue(0, 0);

    for (int kt = 0; kt < nkt; ++kt) {
        const int cur = kt & 1;
        const int k0  = kt * TK;
        const float* Kc = Ks + cur * 64 * 40;
        const float* Vc = Vs + cur * 64 * 36;

        cp_wait<0>();
        __syncthreads();                        // tile kt ready; iter kt-1 fully done
        if (kt + 1 < nkt) issue(kt + 1, cur ^ 1);

        // ---- MMA1: S[k=32][q=64] = K^T Q ----
        float acc[2][4] = {};
        #pragma unroll
        for (int ks = 0; ks < DH; ks += 8) {
            uint32_t af[4], bf[2][2];
            af[0] = f2tf(Kc[(ks + t) * 40 + wk + g]);
            af[1] = f2tf(Kc[(ks + t) * 40 + wk + g + 8]);
            af[2] = f2tf(Kc[(ks + t + 4) * 40 + wk + g]);
            af[3] = f2tf(Kc[(ks + t + 4) * 40 + wk + g + 8]);
            #pragma unroll
            for (int nt = 0; nt < 2; ++nt) {
                int col = wq + nt * 8 + g;
                bf[nt][0] = f2tf(Qs[(ks + t) * 72 + col]);
                bf[nt][1] = f2tf(Qs[(ks + t + 4) * 72 + col]);
            }
            mma_tf32(acc[0], af, bf[0]);
            mma_tf32(acc[1], af, bf[1]);
        }

        // ---- scale + masks; tile max ----
        const int rk0 = k0 + wk + g;
        const float km0 = __ldg(&km[rk0]);
        const float km1 = __ldg(&km[rk0 + 8]);
        float pmax[4];
        const bool diag = (k0 + TK > q0);
        #pragma unroll
        for (int nt = 0; nt < 2; ++nt) {
            int cq = q0 + wq + nt * 8 + 2 * t;
            float a0 = km0, a1 = km0, a2 = km1, a3 = km1;
            if (diag) {
                float2 m0 = *reinterpret_cast<const float2*>(&qm[(size_t)rk0 * SS + cq]);
                float2 m1 = *reinterpret_cast<const float2*>(&qm[(size_t)(rk0 + 8) * SS + cq]);
                a0 += m0.x; a1 += m0.y; a2 += m1.x; a3 += m1.y;
            }
            acc[nt][0] = fmaf(acc[nt][0], 0.125f, a0);
            acc[nt][1] = fmaf(acc[nt][1], 0.125f, a1);
            acc[nt][2] = fmaf(acc[nt][2], 0.125f, a2);
            acc[nt][3] = fmaf(acc[nt][3], 0.125f, a3);
            pmax[nt * 2]     = fmaxf(acc[nt][0], acc[nt][2]);
            pmax[nt * 2 + 1] = fmaxf(acc[nt][1], acc[nt][3]);
        }
        #pragma unroll
        for (int off = 4; off <= 16; off <<= 1)
            #pragma unroll
            for (int i = 0; i < 4; ++i)
                pmax[i] = fmaxf(pmax[i], __shfl_xor_sync(0xffffffffu, pmax[i], off));
        if (g == 0) {
            #pragma unroll
            for (int i = 0; i < 4; ++i)
                red[mh * 64 + wq + (i >> 1) * 8 + 2 * t + (i & 1)] = pmax[i];
        }
        __syncthreads();

        float fac[4];
        #pragma unroll
        for (int i = 0; i < 4; ++i) {
            int col = wq + (i >> 1) * 8 + 2 * t + (i & 1);
            float tm = fmaxf(red[col], red[64 + col]);
            float mn = fmaxf(mC[i], tm);
            fac[i] = __expf(mC[i] - mn);
            mC[i] = mn;
            lC[i] *= fac[i];
        }
        #pragma unroll
        for (int mto = 0; mto < 2; ++mto)
            #pragma unroll
            for (int nt = 0; nt < 2; ++nt) {
                accO[mto][nt][0] *= fac[nt * 2];
                accO[mto][nt][1] *= fac[nt * 2 + 1];
                accO[mto][nt][2] *= fac[nt * 2];
                accO[mto][nt][3] *= fac[nt * 2 + 1];
            }

        // ---- P = exp(S - m) -> Ps; partial sums ----
        float psum[4];
        #pragma unroll
        for (int nt = 0; nt < 2; ++nt) {
            int col = wq + nt * 8 + 2 * t;
            float p0 = __expf(acc[nt][0] - mC[nt * 2]);
            float p1 = __expf(acc[nt][1] - mC[nt * 2 + 1]);
            float p2 = __expf(acc[nt][2] - mC[nt * 2]);
            float p3 = __expf(acc[nt][3] - mC[nt * 2 + 1]);
            psum[nt * 2]     = p0 + p2;
            psum[nt * 2 + 1] = p1 + p3;
            *reinterpret_cast<float2*>(&Ps[(wk + g) * 72 + col])     = make_float2(p0, p1);
            *reinterpret_cast<float2*>(&Ps[(wk + g + 8) * 72 + col]) = make_float2(p2, p3);
        }
        #pragma unroll
        for (int off = 4; off <= 16; off <<= 1)
            #pragma unroll
            for (int i = 0; i < 4; ++i)
                psum[i] += __shfl_xor_sync(0xffffffffu, psum[i], off);
        if (g == 0) {
            #pragma unroll
            for (int i = 0; i < 4; ++i)
                red[mh * 64 + wq + (i >> 1) * 8 + 2 * t + (i & 1)] = psum[i];
        }
        __syncthreads();                        // Ps + sums visible
        #pragma unroll
        for (int i = 0; i < 4; ++i) {
            int col = wq + (i >> 1) * 8 + 2 * t + (i & 1);
            lC[i] += red[col] + red[64 + col];
        }

        // ---- MMA2: O[c=64][q=64] += V @ P ----
        #pragma unroll
        for (int ks = 0; ks < TK; ks += 8) {
            uint32_t af[2][4], bf[2][2];
            #pragma unroll
            for (int mto = 0; mto < 2; ++mto) {
                int row = wc + mto * 16 + g;
                af[mto][0] = f2tf(Vc[row * 36 + ks + t]);
                af[mto][1] = f2tf(Vc[(row + 8) * 36 + ks + t]);
                af[mto][2] = f2tf(Vc[row * 36 + ks + t + 4]);
                af[mto][3] = f2tf(Vc[(row + 8) * 36 + ks + t + 4]);
            }
            #pragma unroll
            for (int nt = 0; nt < 2; ++nt) {
                int col = wq + nt * 8 + g;
                bf[nt][0] = f2tf(Ps[(ks + t) * 72 + col]);
                bf[nt][1] = f2tf(Ps[(ks + t + 4) * 72 + col]);
            }
            #pragma unroll
            for (int mto = 0; mto < 2; ++mto)
                #pragma unroll
                for (int nt = 0; nt < 2; ++nt)
                    mma_tf32(accO[mto][nt], af[mto], bf[nt]);
        }
    }

    // ---- epilogue: O / l -> AT ----
    float* ATz = AT + (size_t)z * DH * SS;
    #pragma unroll
    for (int mto = 0; mto < 2; ++mto) {
        int rc = wc + mto * 16 + g;
        #pragma unroll
        for (int nt = 0; nt < 2; ++nt) {
            int col = q0 + wq + nt * 8 + 2 * t;
            float i0 = 1.f / lC[nt * 2];
            float i1 = 1.f / lC[nt * 2 + 1];
            float2 r0, r1;
            r0.x = accO[mto][nt][0] * i0;
            r0.y = accO[mto][nt][1] * i1;
            r1.x = accO[mto][nt][2] * i0;
            r1.y = accO[mto][nt][3] * i1;
            *reinterpret_cast<float2*>(&ATz[(size_t)rc * SS + col]) = r0;
            *reinterpret_cast<float2*>(&ATz[(size_t)(rc + 8) * SS + col]) = r1;
        }
    }
}

// ============================================================================
extern "C" void kernel_launch(void* const* d_in, const int* in_sizes, int n_in,
                              void* d_out, int out_size)
{
    (void)in_sizes; (void)n_in; (void)out_size;
    const float* q       = (const float*)d_in[0];
    const float* k       = (const float*)d_in[1];
    const float* v       = (const float*)d_in[2];
    const float* qk_mask = (const float*)d_in[3];
    const float* k_mask  = (const float*)d_in[4];
    const float* Wq = (const float*)d_in[5];
    const float* bq = (const float*)d_in[6];
    const float* Wk = (const float*)d_in[7];
    const float* bk = (const float*)d_in[8];
    const float* Wv = (const float*)d_in[9];
    const float* bv = (const float*)d_in[10];
    const float* Wo = (const float*)d_in[11];
    const float* bo = (const float*)d_in[12];
    float* out = (float*)d_out;

    float *QP, *KP, *VP, *AT;
    cudaGetSymbolAddress((void**)&QP, g_QP);
    cudaGetSymbolAddress((void**)&KP, g_KP);
    cudaGetSymbolAddress((void**)&VP, g_VP);
    cudaGetSymbolAddress((void**)&AT, g_AT);

    // 1) merged Q/K/V projections (one launch, 6 z-slices)
    QKVParams p;
    p.W[0] = Wq;  p.W[1] = Wk;  p.W[2] = Wv;
    p.bias[0] = bq; p.bias[1] = bk; p.bias[2] = bv;
    p.X[0] = q;   p.X[1] = k;   p.X[2] = v;
    p.C[0] = QP;  p.C[1] = KP;  p.C[2] = VP;
    qkv_gemm<<<dim3(SS / 128, DD / 128, 6), 256>>>(p);

    // 2) fused flash attention
    const int FL_SMEM = (64 * 72 + 2 * 64 * 40 + 2 * 64 * 36 + 32 * 72 + 128) * 4;
    cudaFuncSetAttribute(flash_attn, cudaFuncAttributeMaxDynamicSharedMemorySize, FL_SMEM);
    flash_attn<<<dim3(SS / TQ, BB * HH), 256, FL_SMEM>>>(QP, KP, VP, qk_mask, k_mask, AT);

    // 3) output projection
    out_gemm<<<dim3(SS / 128, DD / 128, BB), 256>>>(Wo, AT, bo, out);
}

// round 9
// speedup vs baseline: 1.0002x; 1.0002x over previous
#include <cuda_runtime.h>
#include <stdint.h>
#include <math.h>

#define BB 2
#define EE 1024
#define SS 2048
#define HH 16
#define DD 1024
#define DH 64
#define TQ 64
#define TK 32

// ---- scratch (static __device__ arrays; no allocations allowed) ----
__device__ float g_QP[(size_t)BB * DD * SS];
__device__ float g_KP[(size_t)BB * DD * SS];
__device__ float g_VP[(size_t)BB * DD * SS];
__device__ float g_AT[(size_t)BB * DD * SS];

__device__ __forceinline__ uint32_t f2tf(float x) {
    uint32_t u;
    asm("cvt.rna.tf32.f32 %0, %1;" : "=r"(u) : "f"(x));
    return u;
}

__device__ __forceinline__ void mma_tf32(float* c, const uint32_t* a, const uint32_t* b) {
    asm volatile(
        "mma.sync.aligned.m16n8k8.row.col.f32.tf32.tf32.f32 "
        "{%0,%1,%2,%3}, {%4,%5,%6,%7}, {%8,%9}, {%0,%1,%2,%3};"
        : "+f"(c[0]), "+f"(c[1]), "+f"(c[2]), "+f"(c[3])
        : "r"(a[0]), "r"(a[1]), "r"(a[2]), "r"(a[3]), "r"(b[0]), "r"(b[1]));
}

__device__ __forceinline__ void cp16(void* smem, const void* gmem) {
    uint32_t s = (uint32_t)__cvta_generic_to_shared(smem);
    asm volatile("cp.async.cg.shared.global [%0], [%1], 16;\n" :: "r"(s), "l"(gmem));
}
__device__ __forceinline__ void cp_commit() { asm volatile("cp.async.commit_group;\n"); }
template <int N>
__device__ __forceinline__ void cp_wait() { asm volatile("cp.async.wait_group %0;\n" :: "n"(N)); }

// ============================================================================
// Shared tf32 GEMM core: C[m,n] = sum_k A[m,k]*B[k,n] + bias[m].
// 128x128x16 tiles, 3-stage cp.async pipeline, 8 warps (2x4), 64x32 warp tile.
// ============================================================================
template <int BM, int BN>
__device__ __forceinline__ void gemm_core(
    const float* __restrict__ A, const float* __restrict__ Bmat,
    const float* __restrict__ bias, float* __restrict__ C,
    int K, int lda, int ldb, int ldc, int m0, int n0)
{
    constexpr int BK = 16;
    constexpr int THREADS = 256;
    constexpr int MT = 4, NT = 4;
    constexpr int AST = 20;
    constexpr int BST = BN + 8;
    constexpr int STG = 3;
    constexpr int AV = BM * BK / 4 / THREADS;
    constexpr int BV = BK * BN / 4 / THREADS;

    const int niter = K / BK;

    __shared__ __align__(16) float As[STG][BM * AST];
    __shared__ __align__(16) float Bs[STG][BK * BST];

    const int tid  = threadIdx.x;
    const int lane = tid & 31;
    const int wid  = tid >> 5;
    const int g    = lane >> 2;
    const int t    = lane & 3;
    const int wm   = (wid >> 2) * 64;
    const int wn   = (wid & 3) * 32;

    auto issue = [&](int it, int s) {
        const int k0 = it * BK;
        #pragma unroll
        for (int j = 0; j < AV; ++j) {
            int v = tid + j * THREADS;
            int mr = v / (BK / 4), c4 = (v % (BK / 4)) * 4;
            cp16(&As[s][mr * AST + c4], &A[(size_t)(m0 + mr) * lda + k0 + c4]);
        }
        #pragma unroll
        for (int j = 0; j < BV; ++j) {
            int v = tid + j * THREADS;
            int kr = v / (BN / 4), c4 = (v % (BN / 4)) * 4;
            cp16(&Bs[s][kr * BST + c4], &Bmat[(size_t)(k0 + kr) * ldb + n0 + c4]);
        }
        cp_commit();
    };

    float acc[MT][NT][4] = {};

    issue(0, 0);
    if (niter > 1) issue(1, 1);

    for (int i = 0; i < niter; ++i) {
        const int cur = i % STG;
        if (i + 1 < niter) cp_wait<1>(); else cp_wait<0>();
        __syncthreads();
        if (i + 2 < niter) issue(i + 2, (i + 2) % STG);

        #pragma unroll
        for (int ks = 0; ks < BK; ks += 8) {
            uint32_t af[MT][4], bf[NT][2];
            #pragma unroll
            for (int mt = 0; mt < MT; ++mt) {
                int row = wm + mt * 16 + g;
                af[mt][0] = f2tf(As[cur][row * AST + ks + t]);
                af[mt][1] = f2tf(As[cur][(row + 8) * AST + ks + t]);
                af[mt][2] = f2tf(As[cur][row * AST + ks + t + 4]);
                af[mt][3] = f2tf(As[cur][(row + 8) * AST + ks + t + 4]);
            }
            #pragma unroll
            for (int nt = 0; nt < NT; ++nt) {
                int col = wn + nt * 8 + g;
                bf[nt][0] = f2tf(Bs[cur][(ks + t) * BST + col]);
                bf[nt][1] = f2tf(Bs[cur][(ks + t + 4) * BST + col]);
            }
            #pragma unroll
            for (int mt = 0; mt < MT; ++mt)
                #pragma unroll
                for (int nt = 0; nt < NT; ++nt)
                    mma_tf32(acc[mt][nt], af[mt], bf[nt]);
        }
        __syncthreads();
    }

    #pragma unroll
    for (int mt = 0; mt < MT; ++mt) {
        int mg = m0 + wm + mt * 16 + g;
        float b0 = bias ? bias[mg] : 0.f;
        float b1 = bias ? bias[mg + 8] : 0.f;
        #pragma unroll
        for (int nt = 0; nt < NT; ++nt) {
            int n = n0 + wn + nt * 8 + 2 * t;
            float2 r0, r1;
            r0.x = acc[mt][nt][0] + b0;
            r0.y = acc[mt][nt][1] + b0;
            r1.x = acc[mt][nt][2] + b1;
            r1.y = acc[mt][nt][3] + b1;
            *reinterpret_cast<float2*>(&C[(size_t)mg * ldc + n]) = r0;
            *reinterpret_cast<float2*>(&C[(size_t)(mg + 8) * ldc + n]) = r1;
        }
    }
}

struct QKVParams {
    const float* W[3];
    const float* bias[3];
    const float* X[3];
    float* C[3];
};

// merged Q/K/V projections: z = mat*2 + batch
__global__ void __launch_bounds__(256, 2)
qkv_gemm(QKVParams p)
{
    const int mat = blockIdx.z >> 1;
    const int b   = blockIdx.z & 1;
    gemm_core<128, 128>(p.W[mat], p.X[mat] + (size_t)b * EE * SS, p.bias[mat],
                        p.C[mat] + (size_t)b * DD * SS,
                        EE, EE, SS, SS, blockIdx.y * 128, blockIdx.x * 128);
}

// output projection
__global__ void __launch_bounds__(256, 2)
out_gemm(const float* __restrict__ Wo, const float* __restrict__ AT,
         const float* __restrict__ bo, float* __restrict__ out)
{
    const int b = blockIdx.z;
    gemm_core<128, 128>(Wo, AT + (size_t)b * DD * SS, bo,
                        out + (size_t)b * DD * SS,
                        DD, DD, SS, SS, blockIdx.y * 128, blockIdx.x * 128);
}

// ============================================================================
// Fused flash attention. Block = (b*H+h, q-tile of 64). 256 threads, 8 warps.
// Double-buffered K/V (TK=32) via cp.async: tile kt+1 issued right after the
// top-of-iteration sync, overlapping all of compute(kt).
// qk_mask read only on diagonal tiles (k0+TK > q0); k_mask always added.
// Conflict-free smem strides: Qs/Ps 72, Ks 40, Vs 36.
// ============================================================================
__global__ void __launch_bounds__(256, 2)
flash_attn(const float* __restrict__ QP, const float* __restrict__ KP,
           const float* __restrict__ VP, const float* __restrict__ qk_mask,
           const float* __restrict__ k_mask, float* __restrict__ AT)
{
    extern __shared__ __align__(16) float smf[];
    float* Qs = smf;                       // [64 c][64 q] st 72
    float* Ks = Qs + 64 * 72;              // 2 x [64 c][32 k] st 40
    float* Vs = Ks + 2 * 64 * 40;          // 2 x [64 c][32 k] st 36
    float* Ps = Vs + 2 * 64 * 36;          // [32 k][64 q] st 72
    float* red = Ps + 32 * 72;             // [2][64]

    const int z   = blockIdx.y;
    const int b   = z / HH;
    const int q0  = blockIdx.x * TQ;
    const int tid  = threadIdx.x;
    const int lane = tid & 31;
    const int wid  = tid >> 5;
    const int g  = lane >> 2;
    const int t  = lane & 3;
    const int mh = wid >> 2;               // 0/1
    const int wq = (wid & 3) * 16;
    const int wk = mh * 16;                // MMA1 k-half
    const int wc = mh * 32;                // MMA2 c-half

    const float* Qg = QP + (size_t)z * DH * SS;
    const float* Kg = KP + (size_t)z * DH * SS;
    const float* Vg = VP + (size_t)z * DH * SS;
    const float* qm = qk_mask + (size_t)b * SS * SS;
    const float* km = k_mask + (size_t)b * SS;

    // Q tile: 64 rows x 64 cols
    #pragma unroll
    for (int j = 0; j < 4; ++j) {
        int v = tid + j * 256;
        int r = v >> 4, c4 = (v & 15) << 2;
        cp16(&Qs[r * 72 + c4], &Qg[(size_t)r * SS + q0 + c4]);
    }
    cp_commit();

    auto issue = [&](int kt, int s) {
        const int k0 = kt * TK;
        #pragma unroll
        for (int j = 0; j < 2; ++j) {
            int v = tid + j * 256;
            int r = v >> 3, c4 = (v & 7) << 2;
            cp16(&Ks[s * 64 * 40 + r * 40 + c4], &Kg[(size_t)r * SS + k0 + c4]);
            cp16(&Vs[s * 64 * 36 + r * 36 + c4], &Vg[(size_t)r * SS + k0 + c4]);
        }
        cp_commit();
    };

    float accO[2][2][4] = {};
    float mC[4], lC[4];
    #pragma unroll
    for (int i = 0; i < 4; ++i) { mC[i] = -1e30f; lC[i] = 0.f; }

    const int nkt = q0 / TK + 2;
    issue(0, 0);

    for (int kt = 0; kt < nkt; ++kt) {
        const int cur = kt & 1;
        const int k0  = kt * TK;
        const float* Kc = Ks + cur * 64 * 40;
        const float* Vc = Vs + cur * 64 * 36;

        cp_wait<0>();
        __syncthreads();                        // tile kt ready; iter kt-1 fully done
        if (kt + 1 < nkt) issue(kt + 1, cur ^ 1);

        // ---- MMA1: S[k=32][q=64] = K^T Q ----
        float acc[2][4] = {};
        #pragma unroll
        for (int ks = 0; ks < DH; ks += 8) {
            uint32_t af[4], bf[2][2];
            af[0] = f2tf(Kc[(ks + t) * 40 + wk + g]);
            af[1] = f2tf(Kc[(ks + t) * 40 + wk + g + 8]);
            af[2] = f2tf(Kc[(ks + t + 4) * 40 + wk + g]);
            af[3] = f2tf(Kc[(ks + t + 4) * 40 + wk + g + 8]);
            #pragma unroll
            for (int nt = 0; nt < 2; ++nt) {
                int col = wq + nt * 8 + g;
                bf[nt][0] = f2tf(Qs[(ks + t) * 72 + col]);
                bf[nt][1] = f2tf(Qs[(ks + t + 4) * 72 + col]);
            }
            mma_tf32(acc[0], af, bf[0]);
            mma_tf32(acc[1], af, bf[1]);
        }

        // ---- scale + masks; tile max ----
        const int rk0 = k0 + wk + g;
        const float km0 = __ldg(&km[rk0]);
        const float km1 = __ldg(&km[rk0 + 8]);
        float pmax[4];
        const bool diag = (k0 + TK > q0);
        #pragma unroll
        for (int nt = 0; nt < 2; ++nt) {
            int cq = q0 + wq + nt * 8 + 2 * t;
            float a0 = km0, a1 = km0, a2 = km1, a3 = km1;
            if (diag) {
                float2 m0 = *reinterpret_cast<const float2*>(&qm[(size_t)rk0 * SS + cq]);
                float2 m1 = *reinterpret_cast<const float2*>(&qm[(size_t)(rk0 + 8) * SS + cq]);
                a0 += m0.x; a1 += m0.y; a2 += m1.x; a3 += m1.y;
            }
            acc[nt][0] = fmaf(acc[nt][0], 0.125f, a0);
            acc[nt][1] = fmaf(acc[nt][1], 0.125f, a1);
            acc[nt][2] = fmaf(acc[nt][2], 0.125f, a2);
            acc[nt][3] = fmaf(acc[nt][3], 0.125f, a3);
            pmax[nt * 2]     = fmaxf(acc[nt][0], acc[nt][2]);
            pmax[nt * 2 + 1] = fmaxf(acc[nt][1], acc[nt][3]);
        }
        #pragma unroll
        for (int off = 4; off <= 16; off <<= 1)
            #pragma unroll
            for (int i = 0; i < 4; ++i)
                pmax[i] = fmaxf(pmax[i], __shfl_xor_sync(0xffffffffu, pmax[i], off));
        if (g == 0) {
            #pragma unroll
            for (int i = 0; i < 4; ++i)
                red[mh * 64 + wq + (i >> 1) * 8 + 2 * t + (i & 1)] = pmax[i];
        }
        __syncthreads();

        float fac[4];
        #pragma unroll
        for (int i = 0; i < 4; ++i) {
            int col = wq + (i >> 1) * 8 + 2 * t + (i & 1);
            float tm = fmaxf(red[col], red[64 + col]);
            float mn = fmaxf(mC[i], tm);
            fac[i] = __expf(mC[i] - mn);
            mC[i] = mn;
            lC[i] *= fac[i];
        }
        #pragma unroll
        for (int mto = 0; mto < 2; ++mto)
            #pragma unroll
            for (int nt = 0; nt < 2; ++nt) {
                accO[mto][nt][0] *= fac[nt * 2];
                accO[mto][nt][1] *= fac[nt * 2 + 1];
                accO[mto][nt][2] *= fac[nt * 2];
                accO[mto][nt][3] *= fac[nt * 2 + 1];
            }

        // ---- P = exp(S - m) -> Ps; partial sums ----
        float psum[4];
        #pragma unroll
        for (int nt = 0; nt < 2; ++nt) {
            int col = wq + nt * 8 + 2 * t;
            float p0 = __expf(acc[nt][0] - mC[nt * 2]);
            float p1 = __expf(acc[nt][1] - mC[nt * 2 + 1]);
            float p2 = __expf(acc[nt][2] - mC[nt * 2]);
            float p3 = __expf(acc[nt][3] - mC[nt * 2 + 1]);
            psum[nt * 2]     = p0 + p2;
            psum[nt * 2 + 1] = p1 + p3;
            *reinterpret_cast<float2*>(&Ps[(wk + g) * 72 + col])     = make_float2(p0, p1);
            *reinterpret_cast<float2*>(&Ps[(wk + g + 8) * 72 + col]) = make_float2(p2, p3);
        }
        #pragma unroll
        for (int off = 4; off <= 16; off <<= 1)
            #pragma unroll
            for (int i = 0; i < 4; ++i)
                psum[i] += __shfl_xor_sync(0xffffffffu, psum[i], off);
        if (g == 0) {
            #pragma unroll
            for (int i = 0; i < 4; ++i)
                red[mh * 64 + wq + (i >> 1) * 8 + 2 * t + (i & 1)] = psum[i];
        }
        __syncthreads();                        // Ps + sums visible
        #pragma unroll
        for (int i = 0; i < 4; ++i) {
            int col = wq + (i >> 1) * 8 + 2 * t + (i & 1);
            lC[i] += red[col] + red[64 + col];
        }

        // ---- MMA2: O[c=64][q=64] += V @ P ----
        #pragma unroll
        for (int ks = 0; ks < TK; ks += 8) {
            uint32_t af[2][4], bf[2][2];
            #pragma unroll
            for (int mto = 0; mto < 2; ++mto) {
                int row = wc + mto * 16 + g;
                af[mto][0] = f2tf(Vc[row * 36 + ks + t]);
                af[mto][1] = f2tf(Vc[(row + 8) * 36 + ks + t]);
                af[mto][2] = f2tf(Vc[row * 36 + ks + t + 4]);
                af[mto][3] = f2tf(Vc[(row + 8) * 36 + ks + t + 4]);
            }
            #pragma unroll
            for (int nt = 0; nt < 2; ++nt) {
                int col = wq + nt * 8 + g;
                bf[nt][0] = f2tf(Ps[(ks + t) * 72 + col]);
                bf[nt][1] = f2tf(Ps[(ks + t + 4) * 72 + col]);
            }
            #pragma unroll
            for (int mto = 0; mto < 2; ++mto)
                #pragma unroll
                for (int nt = 0; nt < 2; ++nt)
                    mma_tf32(accO[mto][nt], af[mto], bf[nt]);
        }
    }

    // ---- epilogue: O / l -> AT ----
    float* ATz = AT + (size_t)z * DH * SS;
    #pragma unroll
    for (int mto = 0; mto < 2; ++mto) {
        int rc = wc + mto * 16 + g;
        #pragma unroll
        for (int nt = 0; nt < 2; ++nt) {
            int col = q0 + wq + nt * 8 + 2 * t;
            float i0 = 1.f / lC[nt * 2];
            float i1 = 1.f / lC[nt * 2 + 1];
            float2 r0, r1;
            r0.x = accO[mto][nt][0] * i0;
            r0.y = accO[mto][nt][1] * i1;
            r1.x = accO[mto][nt][2] * i0;
            r1.y = accO[mto][nt][3] * i1;
            *reinterpret_cast<float2*>(&ATz[(size_t)rc * SS + col]) = r0;
            *reinterpret_cast<float2*>(&ATz[(size_t)(rc + 8) * SS + col]) = r1;
        }
    }
}

// ============================================================================
extern "C" void kernel_launch(void* const* d_in, const int* in_sizes, int n_in,
                              void* d_out, int out_size)
{
    (void)in_sizes; (void)n_in; (void)out_size;
    const float* q       = (const float*)d_in[0];
    const float* k       = (const float*)d_in[1];
    const float* v       = (const float*)d_in[2];
    const float* qk_mask = (const float*)d_in[3];
    const float* k_mask  = (const float*)d_in[4];
    const float* Wq = (const float*)d_in[5];
    const float* bq = (const float*)d_in[6];
    const float* Wk = (const float*)d_in[7];
    const float* bk = (const float*)d_in[8];
    const float* Wv = (const float*)d_in[9];
    const float* bv = (const float*)d_in[10];
    const float* Wo = (const float*)d_in[11];
    const float* bo = (const float*)d_in[12];
    float* out = (float*)d_out;

    float *QP, *KP, *VP, *AT;
    cudaGetSymbolAddress((void**)&QP, g_QP);
    cudaGetSymbolAddress((void**)&KP, g_KP);
    cudaGetSymbolAddress((void**)&VP, g_VP);
    cudaGetSymbolAddress((void**)&AT, g_AT);

    // 1) merged Q/K/V projections (one launch, 6 z-slices)
    QKVParams p;
    p.W[0] = Wq;  p.W[1] = Wk;  p.W[2] = Wv;
    p.bias[0] = bq; p.bias[1] = bk; p.bias[2] = bv;
    p.X[0] = q;   p.X[1] = k;   p.X[2] = v;
    p.C[0] = QP;  p.C[1] = KP;  p.C[2] = VP;
    qkv_gemm<<<dim3(SS / 128, DD / 128, 6), 256>>>(p);

    // 2) fused flash attention
    const int FL_SMEM = (64 * 72 + 2 * 64 * 40 + 2 * 64 * 36 + 32 * 72 + 128) * 4;
    cudaFuncSetAttribute(flash_attn, cudaFuncAttributeMaxDynamicSharedMemorySize, FL_SMEM);
    flash_attn<<<dim3(SS / TQ, BB * HH), 256, FL_SMEM>>>(QP, KP, VP, qk_mask, k_mask, AT);

    // 3) output projection
    out_gemm<<<dim3(SS / 128, DD / 128, BB), 256>>>(Wo, AT, bo, out);
}

// round 10
// speedup vs baseline: 1.0013x; 1.0011x over previous
#include <cuda_runtime.h>
#include <stdint.h>
#include <math.h>

#define BB 2
#define EE 1024
#define SS 2048
#define HH 16
#define DD 1024
#define DH 64
#define TQ 64
#define TK 32

// ---- scratch (static __device__ arrays; no allocations allowed) ----
__device__ float g_QP[(size_t)BB * DD * SS];
__device__ float g_KP[(size_t)BB * DD * SS];
__device__ float g_VP[(size_t)BB * DD * SS];
__device__ float g_AT[(size_t)BB * DD * SS];

__device__ __forceinline__ uint32_t f2tf(float x) {
    uint32_t u;
    asm("cvt.rna.tf32.f32 %0, %1;" : "=r"(u) : "f"(x));
    return u;
}

__device__ __forceinline__ void mma_tf32(float* c, const uint32_t* a, const uint32_t* b) {
    asm volatile(
        "mma.sync.aligned.m16n8k8.row.col.f32.tf32.tf32.f32 "
        "{%0,%1,%2,%3}, {%4,%5,%6,%7}, {%8,%9}, {%0,%1,%2,%3};"
        : "+f"(c[0]), "+f"(c[1]), "+f"(c[2]), "+f"(c[3])
        : "r"(a[0]), "r"(a[1]), "r"(a[2]), "r"(a[3]), "r"(b[0]), "r"(b[1]));
}

__device__ __forceinline__ void cp16(void* smem, const void* gmem) {
    uint32_t s = (uint32_t)__cvta_generic_to_shared(smem);
    asm volatile("cp.async.cg.shared.global [%0], [%1], 16;\n" :: "r"(s), "l"(gmem));
}
__device__ __forceinline__ void cp_commit() { asm volatile("cp.async.commit_group;\n"); }
template <int N>
__device__ __forceinline__ void cp_wait() { asm volatile("cp.async.wait_group %0;\n" :: "n"(N)); }

// ============================================================================
// Shared tf32 GEMM core: C[m,n] = sum_k A[m,k]*B[k,n] + bias[m].
// 128x128x16 tiles, 3-stage cp.async pipeline, 8 warps (2x4), 64x32 warp tile.
// ============================================================================
template <int BM, int BN>
__device__ __forceinline__ void gemm_core(
    const float* __restrict__ A, const float* __restrict__ Bmat,
    const float* __restrict__ bias, float* __restrict__ C,
    int K, int lda, int ldb, int ldc, int m0, int n0)
{
    constexpr int BK = 16;
    constexpr int THREADS = 256;
    constexpr int MT = 4, NT = 4;
    constexpr int AST = 20;
    constexpr int BST = BN + 8;
    constexpr int STG = 3;
    constexpr int AV = BM * BK / 4 / THREADS;
    constexpr int BV = BK * BN / 4 / THREADS;

    const int niter = K / BK;

    __shared__ __align__(16) float As[STG][BM * AST];
    __shared__ __align__(16) float Bs[STG][BK * BST];

    const int tid  = threadIdx.x;
    const int lane = tid & 31;
    const int wid  = tid >> 5;
    const int g    = lane >> 2;
    const int t    = lane & 3;
    const int wm   = (wid >> 2) * 64;
    const int wn   = (wid & 3) * 32;

    auto issue = [&](int it, int s) {
        const int k0 = it * BK;
        #pragma unroll
        for (int j = 0; j < AV; ++j) {
            int v = tid + j * THREADS;
            int mr = v / (BK / 4), c4 = (v % (BK / 4)) * 4;
            cp16(&As[s][mr * AST + c4], &A[(size_t)(m0 + mr) * lda + k0 + c4]);
        }
        #pragma unroll
        for (int j = 0; j < BV; ++j) {
            int v = tid + j * THREADS;
            int kr = v / (BN / 4), c4 = (v % (BN / 4)) * 4;
            cp16(&Bs[s][kr * BST + c4], &Bmat[(size_t)(k0 + kr) * ldb + n0 + c4]);
        }
        cp_commit();
    };

    float acc[MT][NT][4] = {};

    issue(0, 0);
    if (niter > 1) issue(1, 1);

    for (int i = 0; i < niter; ++i) {
        const int cur = i % STG;
        if (i + 1 < niter) cp_wait<1>(); else cp_wait<0>();
        __syncthreads();
        if (i + 2 < niter) issue(i + 2, (i + 2) % STG);

        #pragma unroll
        for (int ks = 0; ks < BK; ks += 8) {
            uint32_t af[MT][4], bf[NT][2];
            #pragma unroll
            for (int mt = 0; mt < MT; ++mt) {
                int row = wm + mt * 16 + g;
                af[mt][0] = f2tf(As[cur][row * AST + ks + t]);
                af[mt][1] = f2tf(As[cur][(row + 8) * AST + ks + t]);
                af[mt][2] = f2tf(As[cur][row * AST + ks + t + 4]);
                af[mt][3] = f2tf(As[cur][(row + 8) * AST + ks + t + 4]);
            }
            #pragma unroll
            for (int nt = 0; nt < NT; ++nt) {
                int col = wn + nt * 8 + g;
                bf[nt][0] = f2tf(Bs[cur][(ks + t) * BST + col]);
                bf[nt][1] = f2tf(Bs[cur][(ks + t + 4) * BST + col]);
            }
            #pragma unroll
            for (int mt = 0; mt < MT; ++mt)
                #pragma unroll
                for (int nt = 0; nt < NT; ++nt)
                    mma_tf32(acc[mt][nt], af[mt], bf[nt]);
        }
        __syncthreads();
    }

    #pragma unroll
    for (int mt = 0; mt < MT; ++mt) {
        int mg = m0 + wm + mt * 16 + g;
        float b0 = bias ? bias[mg] : 0.f;
        float b1 = bias ? bias[mg + 8] : 0.f;
        #pragma unroll
        for (int nt = 0; nt < NT; ++nt) {
            int n = n0 + wn + nt * 8 + 2 * t;
            float2 r0, r1;
            r0.x = acc[mt][nt][0] + b0;
            r0.y = acc[mt][nt][1] + b0;
            r1.x = acc[mt][nt][2] + b1;
            r1.y = acc[mt][nt][3] + b1;
            *reinterpret_cast<float2*>(&C[(size_t)mg * ldc + n]) = r0;
            *reinterpret_cast<float2*>(&C[(size_t)(mg + 8) * ldc + n]) = r1;
        }
    }
}

struct QKVParams {
    const float* W[3];
    const float* bias[3];
    const float* X[3];
    float* C[3];
};

// merged Q/K/V projections: z = mat*2 + batch
__global__ void __launch_bounds__(256, 2)
qkv_gemm(QKVParams p)
{
    const int mat = blockIdx.z >> 1;
    const int b   = blockIdx.z & 1;
    gemm_core<128, 128>(p.W[mat], p.X[mat] + (size_t)b * EE * SS, p.bias[mat],
                        p.C[mat] + (size_t)b * DD * SS,
                        EE, EE, SS, SS, blockIdx.y * 128, blockIdx.x * 128);
}

// output projection
__global__ void __launch_bounds__(256, 2)
out_gemm(const float* __restrict__ Wo, const float* __restrict__ AT,
         const float* __restrict__ bo, float* __restrict__ out)
{
    const int b = blockIdx.z;
    gemm_core<128, 128>(Wo, AT + (size_t)b * DD * SS, bo,
                        out + (size_t)b * DD * SS,
                        DD, DD, SS, SS, blockIdx.y * 128, blockIdx.x * 128);
}

// ============================================================================
// Fused flash attention. Block = (b*H+h, q-tile of 64). 256 threads, 8 warps.
// Double-buffered K/V (TK=32) via cp.async: tile kt+1 issued right after the
// top-of-iteration sync, overlapping all of compute(kt).
// qk_mask read only on diagonal tiles (k0+TK > q0); k_mask always added.
// Conflict-free smem strides: Qs/Ps 72, Ks 40, Vs 36.
// ============================================================================
__global__ void __launch_bounds__(256, 2)
flash_attn(const float* __restrict__ QP, const float* __restrict__ KP,
           const float* __restrict__ VP, const float* __restrict__ qk_mask,
           const float* __restrict__ k_mask, float* __restrict__ AT)
{
    extern __shared__ __align__(16) float smf[];
    float* Qs = smf;                       // [64 c][64 q] st 72
    float* Ks = Qs + 64 * 72;              // 2 x [64 c][32 k] st 40
    float* Vs = Ks + 2 * 64 * 40;          // 2 x [64 c][32 k] st 36
    float* Ps = Vs + 2 * 64 * 36;          // [32 k][64 q] st 72
    float* red = Ps + 32 * 72;             // [2][64]

    const int z   = blockIdx.y;
    const int b   = z / HH;
    const int q0  = blockIdx.x * TQ;
    const int tid  = threadIdx.x;
    const int lane = tid & 31;
    const int wid  = tid >> 5;
    const int g  = lane >> 2;
    const int t  = lane & 3;
    const int mh = wid >> 2;               // 0/1
    const int wq = (wid & 3) * 16;
    const int wk = mh * 16;                // MMA1 k-half
    const int wc = mh * 32;                // MMA2 c-half

    const float* Qg = QP + (size_t)z * DH * SS;
    const float* Kg = KP + (size_t)z * DH * SS;
    const float* Vg = VP + (size_t)z * DH * SS;
    const float* qm = qk_mask + (size_t)b * SS * SS;
    const float* km = k_mask + (size_t)b * SS;

    // Q tile: 64 rows x 64 cols
    #pragma unroll
    for (int j = 0; j < 4; ++j) {
        int v = tid + j * 256;
        int r = v >> 4, c4 = (v & 15) << 2;
        cp16(&Qs[r * 72 + c4], &Qg[(size_t)r * SS + q0 + c4]);
    }
    cp_commit();

    auto issue = [&](int kt, int s) {
        const int k0 = kt * TK;
        #pragma unroll
        for (int j = 0; j < 2; ++j) {
            int v = tid + j * 256;
            int r = v >> 3, c4 = (v & 7) << 2;
            cp16(&Ks[s * 64 * 40 + r * 40 + c4], &Kg[(size_t)r * SS + k0 + c4]);
            cp16(&Vs[s * 64 * 36 + r * 36 + c4], &Vg[(size_t)r * SS + k0 + c4]);
        }
        cp_commit();
    };

    float accO[2][2][4] = {};
    float mC[4], lC[4];
    #pragma unroll
    for (int i = 0; i < 4; ++i) { mC[i] = -1e30f; lC[i] = 0.f; }

    const int nkt = q0 / TK + 2;
    issue(0, 0);

    for (int kt = 0; kt < nkt; ++kt) {
        const int cur = kt & 1;
        const int k0  = kt * TK;
        const float* Kc = Ks + cur * 64 * 40;
        const float* Vc = Vs + cur * 64 * 36;

        cp_wait<0>();
        __syncthreads();                        // tile kt ready; iter kt-1 fully done
        if (kt + 1 < nkt) issue(kt + 1, cur ^ 1);

        // ---- MMA1: S[k=32][q=64] = K^T Q ----
        float acc[2][4] = {};
        #pragma unroll
        for (int ks = 0; ks < DH; ks += 8) {
            uint32_t af[4], bf[2][2];
            af[0] = f2tf(Kc[(ks + t) * 40 + wk + g]);
            af[1] = f2tf(Kc[(ks + t) * 40 + wk + g + 8]);
            af[2] = f2tf(Kc[(ks + t + 4) * 40 + wk + g]);
            af[3] = f2tf(Kc[(ks + t + 4) * 40 + wk + g + 8]);
            #pragma unroll
            for (int nt = 0; nt < 2; ++nt) {
                int col = wq + nt * 8 + g;
                bf[nt][0] = f2tf(Qs[(ks + t) * 72 + col]);
                bf[nt][1] = f2tf(Qs[(ks + t + 4) * 72 + col]);
            }
            mma_tf32(acc[0], af, bf[0]);
            mma_tf32(acc[1], af, bf[1]);
        }

        // ---- scale + masks; tile max ----
        const int rk0 = k0 + wk + g;
        const float km0 = __ldg(&km[rk0]);
        const float km1 = __ldg(&km[rk0 + 8]);
        float pmax[4];
        const bool diag = (k0 + TK > q0);
        #pragma unroll
        for (int nt = 0; nt < 2; ++nt) {
            int cq = q0 + wq + nt * 8 + 2 * t;
            float a0 = km0, a1 = km0, a2 = km1, a3 = km1;
            if (diag) {
                float2 m0 = *reinterpret_cast<const float2*>(&qm[(size_t)rk0 * SS + cq]);
                float2 m1 = *reinterpret_cast<const float2*>(&qm[(size_t)(rk0 + 8) * SS + cq]);
                a0 += m0.x; a1 += m0.y; a2 += m1.x; a3 += m1.y;
            }
            acc[nt][0] = fmaf(acc[nt][0], 0.125f, a0);
            acc[nt][1] = fmaf(acc[nt][1], 0.125f, a1);
            acc[nt][2] = fmaf(acc[nt][2], 0.125f, a2);
            acc[nt][3] = fmaf(acc[nt][3], 0.125f, a3);
            pmax[nt * 2]     = fmaxf(acc[nt][0], acc[nt][2]);
            pmax[nt * 2 + 1] = fmaxf(acc[nt][1], acc[nt][3]);
        }
        #pragma unroll
        for (int off = 4; off <= 16; off <<= 1)
            #pragma unroll
            for (int i = 0; i < 4; ++i)
                pmax[i] = fmaxf(pmax[i], __shfl_xor_sync(0xffffffffu, pmax[i], off));
        if (g == 0) {
            #pragma unroll
            for (int i = 0; i < 4; ++i)
                red[mh * 64 + wq + (i >> 1) * 8 + 2 * t + (i & 1)] = pmax[i];
        }
        __syncthreads();

        float fac[4];
        #pragma unroll
        for (int i = 0; i < 4; ++i) {
            int col = wq + (i >> 1) * 8 + 2 * t + (i & 1);
            float tm = fmaxf(red[col], red[64 + col]);
            float mn = fmaxf(mC[i], tm);
            fac[i] = __expf(mC[i] - mn);
            mC[i] = mn;
            lC[i] *= fac[i];
        }
        #pragma unroll
        for (int mto = 0; mto < 2; ++mto)
            #pragma unroll
            for (int nt = 0; nt < 2; ++nt) {
                accO[mto][nt][0] *= fac[nt * 2];
                accO[mto][nt][1] *= fac[nt * 2 + 1];
                accO[mto][nt][2] *= fac[nt * 2];
                accO[mto][nt][3] *= fac[nt * 2 + 1];
            }

        // ---- P = exp(S - m) -> Ps; partial sums ----
        float psum[4];
        #pragma unroll
        for (int nt = 0; nt < 2; ++nt) {
            int col = wq + nt * 8 + 2 * t;
            float p0 = __expf(acc[nt][0] - mC[nt * 2]);
            float p1 = __expf(acc[nt][1] - mC[nt * 2 + 1]);
            float p2 = __expf(acc[nt][2] - mC[nt * 2]);
            float p3 = __expf(acc[nt][3] - mC[nt * 2 + 1]);
            psum[nt * 2]     = p0 + p2;
            psum[nt * 2 + 1] = p1 + p3;
            *reinterpret_cast<float2*>(&Ps[(wk + g) * 72 + col])     = make_float2(p0, p1);
            *reinterpret_cast<float2*>(&Ps[(wk + g + 8) * 72 + col]) = make_float2(p2, p3);
        }
        #pragma unroll
        for (int off = 4; off <= 16; off <<= 1)
            #pragma unroll
            for (int i = 0; i < 4; ++i)
                psum[i] += __shfl_xor_sync(0xffffffffu, psum[i], off);
        if (g == 0) {
            #pragma unroll
            for (int i = 0; i < 4; ++i)
                red[mh * 64 + wq + (i >> 1) * 8 + 2 * t + (i & 1)] = psum[i];
        }
        __syncthreads();                        // Ps + sums visible
        #pragma unroll
        for (int i = 0; i < 4; ++i) {
            int col = wq + (i >> 1) * 8 + 2 * t + (i & 1);
            lC[i] += red[col] + red[64 + col];
        }

        // ---- MMA2: O[c=64][q=64] += V @ P ----
        #pragma unroll
        for (int ks = 0; ks < TK; ks += 8) {
            uint32_t af[2][4], bf[2][2];
            #pragma unroll
            for (int mto = 0; mto < 2; ++mto) {
                int row = wc + mto * 16 + g;
                af[mto][0] = f2tf(Vc[row * 36 + ks + t]);
                af[mto][1] = f2tf(Vc[(row + 8) * 36 + ks + t]);
                af[mto][2] = f2tf(Vc[row * 36 + ks + t + 4]);
                af[mto][3] = f2tf(Vc[(row + 8) * 36 + ks + t + 4]);
            }
            #pragma unroll
            for (int nt = 0; nt < 2; ++nt) {
                int col = wq + nt * 8 + g;
                bf[nt][0] = f2tf(Ps[(ks + t) * 72 + col]);
                bf[nt][1] = f2tf(Ps[(ks + t + 4) * 72 + col]);
            }
            #pragma unroll
            for (int mto = 0; mto < 2; ++mto)
                #pragma unroll
                for (int nt = 0; nt < 2; ++nt)
                    mma_tf32(accO[mto][nt], af[mto], bf[nt]);
        }
    }

    // ---- epilogue: O / l -> AT ----
    float* ATz = AT + (size_t)z * DH * SS;
    #pragma unroll
    for (int mto = 0; mto < 2; ++mto) {
        int rc = wc + mto * 16 + g;
        #pragma unroll
        for (int nt = 0; nt < 2; ++nt) {
            int col = q0 + wq + nt * 8 + 2 * t;
            float i0 = 1.f / lC[nt * 2];
            float i1 = 1.f / lC[nt * 2 + 1];
            float2 r0, r1;
            r0.x = accO[mto][nt][0] * i0;
            r0.y = accO[mto][nt][1] * i1;
            r1.x = accO[mto][nt][2] * i0;
            r1.y = accO[mto][nt][3] * i1;
            *reinterpret_cast<float2*>(&ATz[(size_t)rc * SS + col]) = r0;
            *reinterpret_cast<float2*>(&ATz[(size_t)(rc + 8) * SS + col]) = r1;
        }
    }
}

// ============================================================================
extern "C" void kernel_launch(void* const* d_in, const int* in_sizes, int n_in,
                              void* d_out, int out_size)
{
    (void)in_sizes; (void)n_in; (void)out_size;
    const float* q       = (const float*)d_in[0];
    const float* k       = (const float*)d_in[1];
    const float* v       = (const float*)d_in[2];
    const float* qk_mask = (const float*)d_in[3];
    const float* k_mask  = (const float*)d_in[4];
    const float* Wq = (const float*)d_in[5];
    const float* bq = (const float*)d_in[6];
    const float* Wk = (const float*)d_in[7];
    const float* bk = (const float*)d_in[8];
    const float* Wv = (const float*)d_in[9];
    const float* bv = (const float*)d_in[10];
    const float* Wo = (const float*)d_in[11];
    const float* bo = (const float*)d_in[12];
    float* out = (float*)d_out;

    float *QP, *KP, *VP, *AT;
    cudaGetSymbolAddress((void**)&QP, g_QP);
    cudaGetSymbolAddress((void**)&KP, g_KP);
    cudaGetSymbolAddress((void**)&VP, g_VP);
    cudaGetSymbolAddress((void**)&AT, g_AT);

    // 1) merged Q/K/V projections (one launch, 6 z-slices)
    QKVParams p;
    p.W[0] = Wq;  p.W[1] = Wk;  p.W[2] = Wv;
    p.bias[0] = bq; p.bias[1] = bk; p.bias[2] = bv;
    p.X[0] = q;   p.X[1] = k;   p.X[2] = v;
    p.C[0] = QP;  p.C[1] = KP;  p.C[2] = VP;
    qkv_gemm<<<dim3(SS / 128, DD / 128, 6), 256>>>(p);

    // 2) fused flash attention
    const int FL_SMEM = (64 * 72 + 2 * 64 * 40 + 2 * 64 * 36 + 32 * 72 + 128) * 4;
    cudaFuncSetAttribute(flash_attn, cudaFuncAttributeMaxDynamicSharedMemorySize, FL_SMEM);
    flash_attn<<<dim3(SS / TQ, BB * HH), 256, FL_SMEM>>>(QP, KP, VP, qk_mask, k_mask, AT);

    // 3) output projection
    out_gemm<<<dim3(SS / 128, DD / 128, BB), 256>>>(Wo, AT, bo, out);
}

// round 11
// speedup vs baseline: 1.0064x; 1.0051x over previous
#include <cuda_runtime.h>
#include <stdint.h>
#include <math.h>

#define BB 2
#define EE 1024
#define SS 2048
#define HH 16
#define DD 1024
#define DH 64
#define TQ 64
#define TK 32

// ---- scratch (static __device__ arrays; no allocations allowed) ----
__device__ float g_QP[(size_t)BB * DD * SS];
__device__ float g_KP[(size_t)BB * DD * SS];
__device__ float g_VP[(size_t)BB * DD * SS];
__device__ float g_AT[(size_t)BB * DD * SS];

__device__ __forceinline__ uint32_t f2tf(float x) {
    uint32_t u;
    asm("cvt.rna.tf32.f32 %0, %1;" : "=r"(u) : "f"(x));
    return u;
}

__device__ __forceinline__ void mma_tf32(float* c, const uint32_t* a, const uint32_t* b) {
    asm volatile(
        "mma.sync.aligned.m16n8k8.row.col.f32.tf32.tf32.f32 "
        "{%0,%1,%2,%3}, {%4,%5,%6,%7}, {%8,%9}, {%0,%1,%2,%3};"
        : "+f"(c[0]), "+f"(c[1]), "+f"(c[2]), "+f"(c[3])
        : "r"(a[0]), "r"(a[1]), "r"(a[2]), "r"(a[3]), "r"(b[0]), "r"(b[1]));
}

__device__ __forceinline__ void cp16(void* smem, const void* gmem) {
    uint32_t s = (uint32_t)__cvta_generic_to_shared(smem);
    asm volatile("cp.async.cg.shared.global [%0], [%1], 16;\n" :: "r"(s), "l"(gmem));
}
__device__ __forceinline__ void cp_commit() { asm volatile("cp.async.commit_group;\n"); }
template <int N>
__device__ __forceinline__ void cp_wait() { asm volatile("cp.async.wait_group %0;\n" :: "n"(N)); }

// ============================================================================
// Shared tf32 GEMM core: C[m,n] = sum_k A[m,k]*B[k,n] + bias[m].
// 128x128x16 tiles, 3-stage cp.async pipeline, 8 warps (2x4), 64x32 warp tile.
// ============================================================================
template <int BM, int BN>
__device__ __forceinline__ void gemm_core(
    const float* __restrict__ A, const float* __restrict__ Bmat,
    const float* __restrict__ bias, float* __restrict__ C,
    int K, int lda, int ldb, int ldc, int m0, int n0)
{
    constexpr int BK = 16;
    constexpr int THREADS = 256;
    constexpr int MT = 4, NT = 4;
    constexpr int AST = 20;
    constexpr int BST = BN + 8;
    constexpr int STG = 3;
    constexpr int AV = BM * BK / 4 / THREADS;
    constexpr int BV = BK * BN / 4 / THREADS;

    const int niter = K / BK;

    __shared__ __align__(16) float As[STG][BM * AST];
    __shared__ __align__(16) float Bs[STG][BK * BST];

    const int tid  = threadIdx.x;
    const int lane = tid & 31;
    const int wid  = tid >> 5;
    const int g    = lane >> 2;
    const int t    = lane & 3;
    const int wm   = (wid >> 2) * 64;
    const int wn   = (wid & 3) * 32;

    auto issue = [&](int it, int s) {
        const int k0 = it * BK;
        #pragma unroll
        for (int j = 0; j < AV; ++j) {
            int v = tid + j * THREADS;
            int mr = v / (BK / 4), c4 = (v % (BK / 4)) * 4;
            cp16(&As[s][mr * AST + c4], &A[(size_t)(m0 + mr) * lda + k0 + c4]);
        }
        #pragma unroll
        for (int j = 0; j < BV; ++j) {
            int v = tid + j * THREADS;
            int kr = v / (BN / 4), c4 = (v % (BN / 4)) * 4;
            cp16(&Bs[s][kr * BST + c4], &Bmat[(size_t)(k0 + kr) * ldb + n0 + c4]);
        }
        cp_commit();
    };

    float acc[MT][NT][4] = {};

    issue(0, 0);
    if (niter > 1) issue(1, 1);

    for (int i = 0; i < niter; ++i) {
        const int cur = i % STG;
        if (i + 1 < niter) cp_wait<1>(); else cp_wait<0>();
        __syncthreads();
        if (i + 2 < niter) issue(i + 2, (i + 2) % STG);

        #pragma unroll
        for (int ks = 0; ks < BK; ks += 8) {
            uint32_t af[MT][4], bf[NT][2];
            #pragma unroll
            for (int mt = 0; mt < MT; ++mt) {
                int row = wm + mt * 16 + g;
                af[mt][0] = f2tf(As[cur][row * AST + ks + t]);
                af[mt][1] = f2tf(As[cur][(row + 8) * AST + ks + t]);
                af[mt][2] = f2tf(As[cur][row * AST + ks + t + 4]);
                af[mt][3] = f2tf(As[cur][(row + 8) * AST + ks + t + 4]);
            }
            #pragma unroll
            for (int nt = 0; nt < NT; ++nt) {
                int col = wn + nt * 8 + g;
                bf[nt][0] = f2tf(Bs[cur][(ks + t) * BST + col]);
                bf[nt][1] = f2tf(Bs[cur][(ks + t + 4) * BST + col]);
            }
            #pragma unroll
            for (int mt = 0; mt < MT; ++mt)
                #pragma unroll
                for (int nt = 0; nt < NT; ++nt)
                    mma_tf32(acc[mt][nt], af[mt], bf[nt]);
        }
        __syncthreads();
    }

    #pragma unroll
    for (int mt = 0; mt < MT; ++mt) {
        int mg = m0 + wm + mt * 16 + g;
        float b0 = bias ? bias[mg] : 0.f;
        float b1 = bias ? bias[mg + 8] : 0.f;
        #pragma unroll
        for (int nt = 0; nt < NT; ++nt) {
            int n = n0 + wn + nt * 8 + 2 * t;
            float2 r0, r1;
            r0.x = acc[mt][nt][0] + b0;
            r0.y = acc[mt][nt][1] + b0;
            r1.x = acc[mt][nt][2] + b1;
            r1.y = acc[mt][nt][3] + b1;
            *reinterpret_cast<float2*>(&C[(size_t)mg * ldc + n]) = r0;
            *reinterpret_cast<float2*>(&C[(size_t)(mg + 8) * ldc + n]) = r1;
        }
    }
}

struct QKVParams {
    const float* W[3];
    const float* bias[3];
    const float* X[3];
    float* C[3];
};

// merged Q/K/V projections: z = mat*2 + batch
__global__ void __launch_bounds__(256, 2)
qkv_gemm(QKVParams p)
{
    const int mat = blockIdx.z >> 1;
    const int b   = blockIdx.z & 1;
    gemm_core<128, 128>(p.W[mat], p.X[mat] + (size_t)b * EE * SS, p.bias[mat],
                        p.C[mat] + (size_t)b * DD * SS,
                        EE, EE, SS, SS, blockIdx.y * 128, blockIdx.x * 128);
}

// output projection
__global__ void __launch_bounds__(256, 2)
out_gemm(const float* __restrict__ Wo, const float* __restrict__ AT,
         const float* __restrict__ bo, float* __restrict__ out)
{
    const int b = blockIdx.z;
    gemm_core<128, 128>(Wo, AT + (size_t)b * DD * SS, bo,
                        out + (size_t)b * DD * SS,
                        DD, DD, SS, SS, blockIdx.y * 128, blockIdx.x * 128);
}

// ============================================================================
// Fused flash attention. Block = (b*H+h, q-tile of 64). 256 threads, 8 warps.
// Double-buffered K/V (TK=32) via cp.async: tile kt+1 issued right after the
// top-of-iteration sync, overlapping all of compute(kt).
// qk_mask read only on diagonal tiles (k0+TK > q0); k_mask always added.
// Conflict-free smem strides: Qs/Ps 72, Ks 40, Vs 36.
// ============================================================================
__global__ void __launch_bounds__(256, 2)
flash_attn(const float* __restrict__ QP, const float* __restrict__ KP,
           const float* __restrict__ VP, const float* __restrict__ qk_mask,
           const float* __restrict__ k_mask, float* __restrict__ AT)
{
    extern __shared__ __align__(16) float smf[];
    float* Qs = smf;                       // [64 c][64 q] st 72
    float* Ks = Qs + 64 * 72;              // 2 x [64 c][32 k] st 40
    float* Vs = Ks + 2 * 64 * 40;          // 2 x [64 c][32 k] st 36
    float* Ps = Vs + 2 * 64 * 36;          // [32 k][64 q] st 72
    float* red = Ps + 32 * 72;             // [2][64]

    const int z   = blockIdx.y;
    const int b   = z / HH;
    const int q0  = blockIdx.x * TQ;
    const int tid  = threadIdx.x;
    const int lane = tid & 31;
    const int wid  = tid >> 5;
    const int g  = lane >> 2;
    const int t  = lane & 3;
    const int mh = wid >> 2;               // 0/1
    const int wq = (wid & 3) * 16;
    const int wk = mh * 16;                // MMA1 k-half
    const int wc = mh * 32;                // MMA2 c-half

    const float* Qg = QP + (size_t)z * DH * SS;
    const float* Kg = KP + (size_t)z * DH * SS;
    const float* Vg = VP + (size_t)z * DH * SS;
    const float* qm = qk_mask + (size_t)b * SS * SS;
    const float* km = k_mask + (size_t)b * SS;

    // Q tile: 64 rows x 64 cols
    #pragma unroll
    for (int j = 0; j < 4; ++j) {
        int v = tid + j * 256;
        int r = v >> 4, c4 = (v & 15) << 2;
        cp16(&Qs[r * 72 + c4], &Qg[(size_t)r * SS + q0 + c4]);
    }
    cp_commit();

    auto issue = [&](int kt, int s) {
        const int k0 = kt * TK;
        #pragma unroll
        for (int j = 0; j < 2; ++j) {
            int v = tid + j * 256;
            int r = v >> 3, c4 = (v & 7) << 2;
            cp16(&Ks[s * 64 * 40 + r * 40 + c4], &Kg[(size_t)r * SS + k0 + c4]);
            cp16(&Vs[s * 64 * 36 + r * 36 + c4], &Vg[(size_t)r * SS + k0 + c4]);
        }
        cp_commit();
    };

    float accO[2][2][4] = {};
    float mC[4], lC[4];
    #pragma unroll
    for (int i = 0; i < 4; ++i) { mC[i] = -1e30f; lC[i] = 0.f; }

    const int nkt = q0 / TK + 2;
    issue(0, 0);

    for (int kt = 0; kt < nkt; ++kt) {
        const int cur = kt & 1;
        const int k0  = kt * TK;
        const float* Kc = Ks + cur * 64 * 40;
        const float* Vc = Vs + cur * 64 * 36;

        cp_wait<0>();
        __syncthreads();                        // tile kt ready; iter kt-1 fully done
        if (kt + 1 < nkt) issue(kt + 1, cur ^ 1);

        // ---- MMA1: S[k=32][q=64] = K^T Q ----
        float acc[2][4] = {};
        #pragma unroll
        for (int ks = 0; ks < DH; ks += 8) {
            uint32_t af[4], bf[2][2];
            af[0] = f2tf(Kc[(ks + t) * 40 + wk + g]);
            af[1] = f2tf(Kc[(ks + t) * 40 + wk + g + 8]);
            af[2] = f2tf(Kc[(ks + t + 4) * 40 + wk + g]);
            af[3] = f2tf(Kc[(ks + t + 4) * 40 + wk + g + 8]);
            #pragma unroll
            for (int nt = 0; nt < 2; ++nt) {
                int col = wq + nt * 8 + g;
                bf[nt][0] = f2tf(Qs[(ks + t) * 72 + col]);
                bf[nt][1] = f2tf(Qs[(ks + t + 4) * 72 + col]);
            }
            mma_tf32(acc[0], af, bf[0]);
            mma_tf32(acc[1], af, bf[1]);
        }

        // ---- scale + masks; tile max ----
        const int rk0 = k0 + wk + g;
        const float km0 = __ldg(&km[rk0]);
        const float km1 = __ldg(&km[rk0 + 8]);
        float pmax[4];
        const bool diag = (k0 + TK > q0);
        #pragma unroll
        for (int nt = 0; nt < 2; ++nt) {
            int cq = q0 + wq + nt * 8 + 2 * t;
            float a0 = km0, a1 = km0, a2 = km1, a3 = km1;
            if (diag) {
                float2 m0 = *reinterpret_cast<const float2*>(&qm[(size_t)rk0 * SS + cq]);
                float2 m1 = *reinterpret_cast<const float2*>(&qm[(size_t)(rk0 + 8) * SS + cq]);
                a0 += m0.x; a1 += m0.y; a2 += m1.x; a3 += m1.y;
            }
            acc[nt][0] = fmaf(acc[nt][0], 0.125f, a0);
            acc[nt][1] = fmaf(acc[nt][1], 0.125f, a1);
            acc[nt][2] = fmaf(acc[nt][2], 0.125f, a2);
            acc[nt][3] = fmaf(acc[nt][3], 0.125f, a3);
            pmax[nt * 2]     = fmaxf(acc[nt][0], acc[nt][2]);
            pmax[nt * 2 + 1] = fmaxf(acc[nt][1], acc[nt][3]);
        }
        #pragma unroll
        for (int off = 4; off <= 16; off <<= 1)
            #pragma unroll
            for (int i = 0; i < 4; ++i)
                pmax[i] = fmaxf(pmax[i], __shfl_xor_sync(0xffffffffu, pmax[i], off));
        if (g == 0) {
            #pragma unroll
            for (int i = 0; i < 4; ++i)
                red[mh * 64 + wq + (i >> 1) * 8 + 2 * t + (i & 1)] = pmax[i];
        }
        __syncthreads();

        float fac[4];
        #pragma unroll
        for (int i = 0; i < 4; ++i) {
            int col = wq + (i >> 1) * 8 + 2 * t + (i & 1);
            float tm = fmaxf(red[col], red[64 + col]);
            float mn = fmaxf(mC[i], tm);
            fac[i] = __expf(mC[i] - mn);
            mC[i] = mn;
            lC[i] *= fac[i];
        }
        #pragma unroll
        for (int mto = 0; mto < 2; ++mto)
            #pragma unroll
            for (int nt = 0; nt < 2; ++nt) {
                accO[mto][nt][0] *= fac[nt * 2];
                accO[mto][nt][1] *= fac[nt * 2 + 1];
                accO[mto][nt][2] *= fac[nt * 2];
                accO[mto][nt][3] *= fac[nt * 2 + 1];
            }

        // ---- P = exp(S - m) -> Ps; partial sums ----
        float psum[4];
        #pragma unroll
        for (int nt = 0; nt < 2; ++nt) {
            int col = wq + nt * 8 + 2 * t;
            float p0 = __expf(acc[nt][0] - mC[nt * 2]);
            float p1 = __expf(acc[nt][1] - mC[nt * 2 + 1]);
            float p2 = __expf(acc[nt][2] - mC[nt * 2]);
            float p3 = __expf(acc[nt][3] - mC[nt * 2 + 1]);
            psum[nt * 2]     = p0 + p2;
            psum[nt * 2 + 1] = p1 + p3;
            *reinterpret_cast<float2*>(&Ps[(wk + g) * 72 + col])     = make_float2(p0, p1);
            *reinterpret_cast<float2*>(&Ps[(wk + g + 8) * 72 + col]) = make_float2(p2, p3);
        }
        #pragma unroll
        for (int off = 4; off <= 16; off <<= 1)
            #pragma unroll
            for (int i = 0; i < 4; ++i)
                psum[i] += __shfl_xor_sync(0xffffffffu, psum[i], off);
        if (g == 0) {
            #pragma unroll
            for (int i = 0; i < 4; ++i)
                red[mh * 64 + wq + (i >> 1) * 8 + 2 * t + (i & 1)] = psum[i];
        }
        __syncthreads();                        // Ps + sums visible
        #pragma unroll
        for (int i = 0; i < 4; ++i) {
            int col = wq + (i >> 1) * 8 + 2 * t + (i & 1);
            lC[i] += red[col] + red[64 + col];
        }

        // ---- MMA2: O[c=64][q=64] += V @ P ----
        #pragma unroll
        for (int ks = 0; ks < TK; ks += 8) {
            uint32_t af[2][4], bf[2][2];
            #pragma unroll
            for (int mto = 0; mto < 2; ++mto) {
                int row = wc + mto * 16 + g;
                af[mto][0] = f2tf(Vc[row * 36 + ks + t]);
                af[mto][1] = f2tf(Vc[(row + 8) * 36 + ks + t]);
                af[mto][2] = f2tf(Vc[row * 36 + ks + t + 4]);
                af[mto][3] = f2tf(Vc[(row + 8) * 36 + ks + t + 4]);
            }
            #pragma unroll
            for (int nt = 0; nt < 2; ++nt) {
                int col = wq + nt * 8 + g;
                bf[nt][0] = f2tf(Ps[(ks + t) * 72 + col]);
                bf[nt][1] = f2tf(Ps[(ks + t + 4) * 72 + col]);
            }
            #pragma unroll
            for (int mto = 0; mto < 2; ++mto)
                #pragma unroll
                for (int nt = 0; nt < 2; ++nt)
                    mma_tf32(accO[mto][nt], af[mto], bf[nt]);
        }
    }

    // ---- epilogue: O / l -> AT ----
    float* ATz = AT + (size_t)z * DH * SS;
    #pragma unroll
    for (int mto = 0; mto < 2; ++mto) {
        int rc = wc + mto * 16 + g;
        #pragma unroll
        for (int nt = 0; nt < 2; ++nt) {
            int col = q0 + wq + nt * 8 + 2 * t;
            float i0 = 1.f / lC[nt * 2];
            float i1 = 1.f / lC[nt * 2 + 1];
            float2 r0, r1;
            r0.x = accO[mto][nt][0] * i0;
            r0.y = accO[mto][nt][1] * i1;
            r1.x = accO[mto][nt][2] * i0;
            r1.y = accO[mto][nt][3] * i1;
            *reinterpret_cast<float2*>(&ATz[(size_t)rc * SS + col]) = r0;
            *reinterpret_cast<float2*>(&ATz[(size_t)(rc + 8) * SS + col]) = r1;
        }
    }
}

// ============================================================================
extern "C" void kernel_launch(void* const* d_in, const int* in_sizes, int n_in,
                              void* d_out, int out_size)
{
    (void)in_sizes; (void)n_in; (void)out_size;
    const float* q       = (const float*)d_in[0];
    const float* k       = (const float*)d_in[1];
    const float* v       = (const float*)d_in[2];
    const float* qk_mask = (const float*)d_in[3];
    const float* k_mask  = (const float*)d_in[4];
    const float* Wq = (const float*)d_in[5];
    const float* bq = (const float*)d_in[6];
    const float* Wk = (const float*)d_in[7];
    const float* bk = (const float*)d_in[8];
    const float* Wv = (const float*)d_in[9];
    const float* bv = (const float*)d_in[10];
    const float* Wo = (const float*)d_in[11];
    const float* bo = (const float*)d_in[12];
    float* out = (float*)d_out;

    float *QP, *KP, *VP, *AT;
    cudaGetSymbolAddress((void**)&QP, g_QP);
    cudaGetSymbolAddress((void**)&KP, g_KP);
    cudaGetSymbolAddress((void**)&VP, g_VP);
    cudaGetSymbolAddress((void**)&AT, g_AT);

    // 1) merged Q/K/V projections (one launch, 6 z-slices)
    QKVParams p;
    p.W[0] = Wq;  p.W[1] = Wk;  p.W[2] = Wv;
    p.bias[0] = bq; p.bias[1] = bk; p.bias[2] = bv;
    p.X[0] = q;   p.X[1] = k;   p.X[2] = v;
    p.C[0] = QP;  p.C[1] = KP;  p.C[2] = VP;
    qkv_gemm<<<dim3(SS / 128, DD / 128, 6), 256>>>(p);

    // 2) fused flash attention
    const int FL_SMEM = (64 * 72 + 2 * 64 * 40 + 2 * 64 * 36 + 32 * 72 + 128) * 4;
    cudaFuncSetAttribute(flash_attn, cudaFuncAttributeMaxDynamicSharedMemorySize, FL_SMEM);
    flash_attn<<<dim3(SS / TQ, BB * HH), 256, FL_SMEM>>>(QP, KP, VP, qk_mask, k_mask, AT);

    // 3) output projection
    out_gemm<<<dim3(SS / 128, DD / 128, BB), 256>>>(Wo, AT, bo, out);
}